// round 9
// baseline (speedup 1.0000x reference)
#include <cuda_runtime.h>
#include <cuda_bf16.h>

#define N_NODES 50000
#define N_EDGES 800000
#define D 64

// ---------------- device scratch (no allocations allowed) ----------------
__device__ int   g_deg[N_NODES];
__device__ int   g_cnt[N_NODES];
__device__ int   g_row[N_NODES + 1];
__device__ int   g_src[N_EDGES];
__device__ float g_dis[N_NODES];
__device__ float g_xw[N_NODES * D];
__device__ float g_agg[N_NODES * D];
__device__ int   g_is64;   // 1 if edge_index is int64-layout, 0 if int32

// ---------------- dtype probe + zero ----------------
__global__ void k_zero() {
    int i = blockIdx.x * blockDim.x + threadIdx.x;
    if (i == 0) g_is64 = 1;          // assume int64 until a nonzero odd word found
    if (i < N_NODES) { g_deg[i] = 0; g_cnt[i] = 0; }
}

// If the buffer holds int64 values < 2^31, every odd 32-bit word is 0.
// If it holds int32 node ids, odd words are random ids in [0,50000) — among
// 65536 samples at least one is nonzero with overwhelming probability.
__global__ void k_probe(const int* __restrict__ ei32) {
    int i = blockIdx.x * blockDim.x + threadIdx.x;
    if (i < 65536) {
        if (ei32[2 * i + 1] != 0) g_is64 = 0;   // racy but idempotent store
    }
}

__device__ __forceinline__ int load_idx(const void* ei, long long pos) {
    if (g_is64) return (int)((const long long*)ei)[pos];
    return ((const int*)ei)[pos];
}

// ---------------- CSR build ----------------
__global__ void k_hist(const void* __restrict__ ei) {
    int e = blockIdx.x * blockDim.x + threadIdx.x;
    if (e < N_EDGES) {
        int d = load_idx(ei, (long long)N_EDGES + e);
        if ((unsigned)d < N_NODES) atomicAdd(&g_deg[d], 1);
    }
}

__global__ void k_dis() {
    int i = blockIdx.x * blockDim.x + threadIdx.x;
    if (i < N_NODES) g_dis[i] = rsqrtf((float)(g_deg[i] + 1));  // +1 self loop
}

// single-block exclusive scan over g_deg -> g_row
__global__ void k_scan() {
    __shared__ int sh[32];
    int tid  = threadIdx.x;
    int lan  = tid & 31;
    int wrp  = tid >> 5;
    int carry = 0;
    for (int base = 0; base < N_NODES; base += 1024) {
        int i = base + tid;
        int v = (i < N_NODES) ? g_deg[i] : 0;
        int x = v;
        #pragma unroll
        for (int d = 1; d < 32; d <<= 1) {
            int y = __shfl_up_sync(0xffffffffu, x, d);
            if (lan >= d) x += y;
        }
        if (lan == 31) sh[wrp] = x;
        __syncthreads();
        if (tid < 32) {
            int y = sh[tid];
            #pragma unroll
            for (int d = 1; d < 32; d <<= 1) {
                int z = __shfl_up_sync(0xffffffffu, y, d);
                if (tid >= d) y += z;
            }
            sh[tid] = y;
        }
        __syncthreads();
        int add  = (wrp > 0) ? sh[wrp - 1] : 0;
        int incl = x + add;
        if (i < N_NODES) g_row[i] = carry + incl - v;   // exclusive
        if (i == N_NODES - 1) g_row[N_NODES] = carry + incl;
        carry += sh[31];
        __syncthreads();
    }
}

__global__ void k_fill(const void* __restrict__ ei) {
    int e = blockIdx.x * blockDim.x + threadIdx.x;
    if (e < N_EDGES) {
        int s = load_idx(ei, e);
        int d = load_idx(ei, (long long)N_EDGES + e);
        if ((unsigned)d < N_NODES && (unsigned)s < N_NODES) {
            int pos = g_row[d] + atomicAdd(&g_cnt[d], 1);
            if ((unsigned)pos < N_EDGES) g_src[pos] = s;
        }
    }
}

// ---------------- GEMM: g_xw = in @ W  (in: [N,64], W: [64,64]) ----------------
// FIRST=true reads harness input x; otherwise reads the device global g_agg
// (device globals must NOT be passed as kernel args from host code).
// 256 threads / block, 128 rows / block, 2 threads per row (32 cols each).
template <bool FIRST>
__global__ void __launch_bounds__(256) k_gemm(const float* __restrict__ x,
                                              const float* __restrict__ W) {
    __shared__ float Ws[D * D];
    int tid = threadIdx.x;
    #pragma unroll
    for (int i = tid; i < D * D; i += 256) Ws[i] = W[i];
    __syncthreads();

    const float* in = FIRST ? x : (const float*)g_agg;

    int row  = blockIdx.x * 128 + (tid & 127);
    int half = tid >> 7;                 // threads 0-127: half 0, 128-255: half 1
    if (row >= N_NODES) return;

    float acc[32];
    #pragma unroll
    for (int c = 0; c < 32; c++) acc[c] = 0.f;

    const float4* inr = reinterpret_cast<const float4*>(in + row * D);
    #pragma unroll
    for (int kk = 0; kk < 16; kk++) {
        float4 xv = inr[kk];
        #pragma unroll
        for (int j = 0; j < 4; j++) {
            int k = kk * 4 + j;
            float xs = (j == 0) ? xv.x : (j == 1) ? xv.y : (j == 2) ? xv.z : xv.w;
            const float4* wr = reinterpret_cast<const float4*>(&Ws[k * D + half * 32]);
            #pragma unroll
            for (int c4 = 0; c4 < 8; c4++) {
                float4 w = wr[c4];   // broadcast: whole warp reads same address
                acc[c4 * 4 + 0] += xs * w.x;
                acc[c4 * 4 + 1] += xs * w.y;
                acc[c4 * 4 + 2] += xs * w.z;
                acc[c4 * 4 + 3] += xs * w.w;
            }
        }
    }
    float4* o = reinterpret_cast<float4*>(g_xw + row * D + half * 32);
    #pragma unroll
    for (int c4 = 0; c4 < 8; c4++)
        o[c4] = make_float4(acc[c4 * 4], acc[c4 * 4 + 1], acc[c4 * 4 + 2], acc[c4 * 4 + 3]);
}

// ---------------- aggregation: one warp per node ----------------
// acc = dis[v]^2 * xw[v] + sum_{e in CSR(v)} dis[src]*dis[v] * xw[src]
// then relu(acc + bias).  FINAL layer additionally applies the 64->8 head.
template <bool FINAL>
__global__ void __launch_bounds__(256) k_aggr(const float* __restrict__ bias,
                                              const float* __restrict__ linW,
                                              const float* __restrict__ linb,
                                              float* __restrict__ out) {
    __shared__ float lW[512 + 8];
    if (FINAL) {
        for (int i = threadIdx.x; i < 512; i += blockDim.x) lW[i] = linW[i];
        if (threadIdx.x < 8) lW[512 + threadIdx.x] = linb[threadIdx.x];
        __syncthreads();
    }
    int v    = (blockIdx.x * blockDim.x + threadIdx.x) >> 5;
    int lane = threadIdx.x & 31;
    if (v >= N_NODES) return;

    float dv = g_dis[v];
    float sl = dv * dv;
    float acc0 = g_xw[v * D + lane]      * sl;
    float acc1 = g_xw[v * D + 32 + lane] * sl;

    int e = g_row[v], end = g_row[v + 1];
    for (; e + 2 <= end; e += 2) {
        int   s0 = g_src[e],       s1 = g_src[e + 1];
        float n0 = g_dis[s0] * dv, n1 = g_dis[s1] * dv;
        float a0 = g_xw[s0 * D + lane],      a1 = g_xw[s0 * D + 32 + lane];
        float c0 = g_xw[s1 * D + lane],      c1 = g_xw[s1 * D + 32 + lane];
        acc0 += a0 * n0 + c0 * n1;
        acc1 += a1 * n0 + c1 * n1;
    }
    if (e < end) {
        int   s = g_src[e];
        float n = g_dis[s] * dv;
        acc0 += g_xw[s * D + lane]      * n;
        acc1 += g_xw[s * D + 32 + lane] * n;
    }

    acc0 = fmaxf(acc0 + bias[lane],      0.f);
    acc1 = fmaxf(acc1 + bias[32 + lane], 0.f);

    if (!FINAL) {
        g_agg[v * D + lane]      = acc0;
        g_agg[v * D + 32 + lane] = acc1;
    } else {
        float myout = 0.f;
        #pragma unroll
        for (int o = 0; o < 8; o++) {
            float p = acc0 * lW[lane * 8 + o] + acc1 * lW[(lane + 32) * 8 + o];
            #pragma unroll
            for (int d = 16; d; d >>= 1) p += __shfl_xor_sync(0xffffffffu, p, d);
            if (lane == o) myout = p + lW[512 + o];
        }
        if (lane < 8) out[v * 8 + lane] = myout;
    }
}

// ---------------- launch ----------------
extern "C" void kernel_launch(void* const* d_in, const int* in_sizes, int n_in,
                              void* d_out, int out_size) {
    const float* x   = (const float*)d_in[0];
    const void*  ei  = d_in[1];
    const float* W0  = (const float*)d_in[2];
    const float* b0  = (const float*)d_in[3];
    const float* W1  = (const float*)d_in[4];
    const float* b1  = (const float*)d_in[5];
    const float* W2  = (const float*)d_in[6];
    const float* b2  = (const float*)d_in[7];
    const float* lW  = (const float*)d_in[8];
    const float* lb  = (const float*)d_in[9];
    float*       out = (float*)d_out;

    const int NB_N = (N_NODES + 255) / 256;      // 196
    const int NB_E = (N_EDGES + 255) / 256;      // 3125
    const int NB_G = (N_NODES + 127) / 128;      // 391
    const int NB_A = (N_NODES * 32 + 255) / 256; // 6250

    // CSR build (per-call, graph-capturable, allocation-free)
    k_zero <<<NB_N, 256>>>();
    k_probe<<<256, 256>>>((const int*)ei);
    k_hist <<<NB_E, 256>>>(ei);
    k_dis  <<<NB_N, 256>>>();
    k_scan <<<1, 1024>>>();
    k_fill <<<NB_E, 256>>>(ei);

    // layer 0
    k_gemm<true><<<NB_G, 256>>>(x, W0);
    k_aggr<false><<<NB_A, 256>>>(b0, nullptr, nullptr, nullptr);
    // layer 1
    k_gemm<false><<<NB_G, 256>>>(nullptr, W1);
    k_aggr<false><<<NB_A, 256>>>(b1, nullptr, nullptr, nullptr);
    // layer 2 + fused 64->8 head
    k_gemm<false><<<NB_G, 256>>>(nullptr, W2);
    k_aggr<true><<<NB_A, 256>>>(b2, lW, lb, out);
}

// round 10
// speedup vs baseline: 1.0048x; 1.0048x over previous
#include <cuda_runtime.h>
#include <cuda_bf16.h>

#define N_NODES 50000
#define N_EDGES 800000
#define D 64

// ---------------- device scratch (no allocations allowed) ----------------
__device__ int   g_deg[N_NODES];
__device__ int   g_cnt[N_NODES];
__device__ int   g_row[N_NODES + 1];
__device__ int   g_src[N_EDGES];
__device__ float g_dis[N_NODES];
__device__ float g_xw[N_NODES * D];
__device__ float g_agg[N_NODES * D];
__device__ int   g_is64;   // 1 if edge_index is int64-layout, 0 if int32

// ---------------- dtype probe + zero ----------------
__global__ void k_zero() {
    int i = blockIdx.x * blockDim.x + threadIdx.x;
    if (i == 0) g_is64 = 1;          // assume int64 until a nonzero odd word found
    if (i < N_NODES) { g_deg[i] = 0; g_cnt[i] = 0; }
}

// If the buffer holds int64 values < 2^31, every odd 32-bit word is 0.
// If it holds int32 node ids, odd words are random ids in [0,50000) — among
// 65536 samples at least one is nonzero with overwhelming probability.
__global__ void k_probe(const int* __restrict__ ei32) {
    int i = blockIdx.x * blockDim.x + threadIdx.x;
    if (i < 65536) {
        if (ei32[2 * i + 1] != 0) g_is64 = 0;   // racy but idempotent store
    }
}

__device__ __forceinline__ int load_idx(const void* ei, long long pos) {
    if (g_is64) return (int)((const long long*)ei)[pos];
    return ((const int*)ei)[pos];
}

// ---------------- CSR build ----------------
__global__ void k_hist(const void* __restrict__ ei) {
    int e = blockIdx.x * blockDim.x + threadIdx.x;
    if (e < N_EDGES) {
        int d = load_idx(ei, (long long)N_EDGES + e);
        if ((unsigned)d < N_NODES) atomicAdd(&g_deg[d], 1);
    }
}

__global__ void k_dis() {
    int i = blockIdx.x * blockDim.x + threadIdx.x;
    if (i < N_NODES) g_dis[i] = rsqrtf((float)(g_deg[i] + 1));  // +1 self loop
}

// single-block exclusive scan over g_deg -> g_row
__global__ void k_scan() {
    __shared__ int sh[32];
    int tid  = threadIdx.x;
    int lan  = tid & 31;
    int wrp  = tid >> 5;
    int carry = 0;
    for (int base = 0; base < N_NODES; base += 1024) {
        int i = base + tid;
        int v = (i < N_NODES) ? g_deg[i] : 0;
        int x = v;
        #pragma unroll
        for (int d = 1; d < 32; d <<= 1) {
            int y = __shfl_up_sync(0xffffffffu, x, d);
            if (lan >= d) x += y;
        }
        if (lan == 31) sh[wrp] = x;
        __syncthreads();
        if (tid < 32) {
            int y = sh[tid];
            #pragma unroll
            for (int d = 1; d < 32; d <<= 1) {
                int z = __shfl_up_sync(0xffffffffu, y, d);
                if (tid >= d) y += z;
            }
            sh[tid] = y;
        }
        __syncthreads();
        int add  = (wrp > 0) ? sh[wrp - 1] : 0;
        int incl = x + add;
        if (i < N_NODES) g_row[i] = carry + incl - v;   // exclusive
        if (i == N_NODES - 1) g_row[N_NODES] = carry + incl;
        carry += sh[31];
        __syncthreads();
    }
}

__global__ void k_fill(const void* __restrict__ ei) {
    int e = blockIdx.x * blockDim.x + threadIdx.x;
    if (e < N_EDGES) {
        int s = load_idx(ei, e);
        int d = load_idx(ei, (long long)N_EDGES + e);
        if ((unsigned)d < N_NODES && (unsigned)s < N_NODES) {
            int pos = g_row[d] + atomicAdd(&g_cnt[d], 1);
            if ((unsigned)pos < N_EDGES) g_src[pos] = s;
        }
    }
}

// ---------------- GEMM: g_xw = in @ W  (in: [N,64], W: [64,64]) ----------------
// FIRST=true reads harness input x; otherwise reads the device global g_agg
// (device globals must NOT be passed as kernel args from host code).
// 256 threads / block, 128 rows / block, 2 threads per row (32 cols each).
template <bool FIRST>
__global__ void __launch_bounds__(256) k_gemm(const float* __restrict__ x,
                                              const float* __restrict__ W) {
    __shared__ float Ws[D * D];
    int tid = threadIdx.x;
    #pragma unroll
    for (int i = tid; i < D * D; i += 256) Ws[i] = W[i];
    __syncthreads();

    const float* in = FIRST ? x : (const float*)g_agg;

    int row  = blockIdx.x * 128 + (tid & 127);
    int half = tid >> 7;                 // threads 0-127: half 0, 128-255: half 1
    if (row >= N_NODES) return;

    float acc[32];
    #pragma unroll
    for (int c = 0; c < 32; c++) acc[c] = 0.f;

    const float4* inr = reinterpret_cast<const float4*>(in + row * D);
    #pragma unroll
    for (int kk = 0; kk < 16; kk++) {
        float4 xv = inr[kk];
        #pragma unroll
        for (int j = 0; j < 4; j++) {
            int k = kk * 4 + j;
            float xs = (j == 0) ? xv.x : (j == 1) ? xv.y : (j == 2) ? xv.z : xv.w;
            const float4* wr = reinterpret_cast<const float4*>(&Ws[k * D + half * 32]);
            #pragma unroll
            for (int c4 = 0; c4 < 8; c4++) {
                float4 w = wr[c4];   // broadcast: whole warp reads same address
                acc[c4 * 4 + 0] += xs * w.x;
                acc[c4 * 4 + 1] += xs * w.y;
                acc[c4 * 4 + 2] += xs * w.z;
                acc[c4 * 4 + 3] += xs * w.w;
            }
        }
    }
    float4* o = reinterpret_cast<float4*>(g_xw + row * D + half * 32);
    #pragma unroll
    for (int c4 = 0; c4 < 8; c4++)
        o[c4] = make_float4(acc[c4 * 4], acc[c4 * 4 + 1], acc[c4 * 4 + 2], acc[c4 * 4 + 3]);
}

// ---------------- aggregation: one warp per node ----------------
// acc = dis[v]^2 * xw[v] + sum_{e in CSR(v)} dis[src]*dis[v] * xw[src]
// then relu(acc + bias).  FINAL layer additionally applies the 64->8 head.
template <bool FINAL>
__global__ void __launch_bounds__(256) k_aggr(const float* __restrict__ bias,
                                              const float* __restrict__ linW,
                                              const float* __restrict__ linb,
                                              float* __restrict__ out) {
    __shared__ float lW[512 + 8];
    if (FINAL) {
        for (int i = threadIdx.x; i < 512; i += blockDim.x) lW[i] = linW[i];
        if (threadIdx.x < 8) lW[512 + threadIdx.x] = linb[threadIdx.x];
        __syncthreads();
    }
    int v    = (blockIdx.x * blockDim.x + threadIdx.x) >> 5;
    int lane = threadIdx.x & 31;
    if (v >= N_NODES) return;

    float dv = g_dis[v];
    float sl = dv * dv;
    float acc0 = g_xw[v * D + lane]      * sl;
    float acc1 = g_xw[v * D + 32 + lane] * sl;

    int e = g_row[v], end = g_row[v + 1];
    for (; e + 2 <= end; e += 2) {
        int   s0 = g_src[e],       s1 = g_src[e + 1];
        float n0 = g_dis[s0] * dv, n1 = g_dis[s1] * dv;
        float a0 = g_xw[s0 * D + lane],      a1 = g_xw[s0 * D + 32 + lane];
        float c0 = g_xw[s1 * D + lane],      c1 = g_xw[s1 * D + 32 + lane];
        acc0 += a0 * n0 + c0 * n1;
        acc1 += a1 * n0 + c1 * n1;
    }
    if (e < end) {
        int   s = g_src[e];
        float n = g_dis[s] * dv;
        acc0 += g_xw[s * D + lane]      * n;
        acc1 += g_xw[s * D + 32 + lane] * n;
    }

    acc0 = fmaxf(acc0 + bias[lane],      0.f);
    acc1 = fmaxf(acc1 + bias[32 + lane], 0.f);

    if (!FINAL) {
        g_agg[v * D + lane]      = acc0;
        g_agg[v * D + 32 + lane] = acc1;
    } else {
        float myout = 0.f;
        #pragma unroll
        for (int o = 0; o < 8; o++) {
            float p = acc0 * lW[lane * 8 + o] + acc1 * lW[(lane + 32) * 8 + o];
            #pragma unroll
            for (int d = 16; d; d >>= 1) p += __shfl_xor_sync(0xffffffffu, p, d);
            if (lane == o) myout = p + lW[512 + o];
        }
        if (lane < 8) out[v * 8 + lane] = myout;
    }
}

// ---------------- launch ----------------
extern "C" void kernel_launch(void* const* d_in, const int* in_sizes, int n_in,
                              void* d_out, int out_size) {
    const float* x   = (const float*)d_in[0];
    const void*  ei  = d_in[1];
    const float* W0  = (const float*)d_in[2];
    const float* b0  = (const float*)d_in[3];
    const float* W1  = (const float*)d_in[4];
    const float* b1  = (const float*)d_in[5];
    const float* W2  = (const float*)d_in[6];
    const float* b2  = (const float*)d_in[7];
    const float* lW  = (const float*)d_in[8];
    const float* lb  = (const float*)d_in[9];
    float*       out = (float*)d_out;

    const int NB_N = (N_NODES + 255) / 256;      // 196
    const int NB_E = (N_EDGES + 255) / 256;      // 3125
    const int NB_G = (N_NODES + 127) / 128;      // 391
    const int NB_A = (N_NODES * 32 + 255) / 256; // 6250

    // CSR build (per-call, graph-capturable, allocation-free)
    k_zero <<<NB_N, 256>>>();
    k_probe<<<256, 256>>>((const int*)ei);
    k_hist <<<NB_E, 256>>>(ei);
    k_dis  <<<NB_N, 256>>>();
    k_scan <<<1, 1024>>>();
    k_fill <<<NB_E, 256>>>(ei);

    // layer 0
    k_gemm<true><<<NB_G, 256>>>(x, W0);
    k_aggr<false><<<NB_A, 256>>>(b0, nullptr, nullptr, nullptr);
    // layer 1
    k_gemm<false><<<NB_G, 256>>>(nullptr, W1);
    k_aggr<false><<<NB_A, 256>>>(b1, nullptr, nullptr, nullptr);
    // layer 2 + fused 64->8 head
    k_gemm<false><<<NB_G, 256>>>(nullptr, W2);
    k_aggr<true><<<NB_A, 256>>>(b2, lW, lb, out);
}